// round 4
// baseline (speedup 1.0000x reference)
#include <cuda_runtime.h>
#include <cstdint>

#define NMAX 100000
#define DD 64

static __device__ float g_k[NMAX * DD];
static __device__ float g_q[NMAX * DD];
static __device__ float g_v[NMAX * DD];
static __device__ float g_agg[NMAX * DD];

__device__ __forceinline__ void red_add_v4(float* p, float a, float b, float c, float d) {
    asm volatile("red.global.add.v4.f32 [%0], {%1,%2,%3,%4};"
                 :: "l"(p), "f"(a), "f"(b), "f"(c), "f"(d) : "memory");
}
__device__ __forceinline__ unsigned long long pack_dup(float v) {
    unsigned long long r;
    asm("mov.b64 %0, {%1, %2};" : "=l"(r) : "f"(v), "f"(v));
    return r;
}
__device__ __forceinline__ void ffma2(unsigned long long& d,
                                      unsigned long long a, unsigned long long b) {
    asm("fma.rn.f32x2 %0, %1, %2, %0;" : "+l"(d) : "l"(a), "l"(b));
}
__device__ __forceinline__ float2 unpack2(unsigned long long v) {
    float lo, hi;
    asm("mov.b64 {%0, %1}, %2;" : "=f"(lo), "=f"(hi) : "l"(v));
    return make_float2(lo, hi);
}
__device__ __forceinline__ void cp_async16(unsigned int saddr, const float* gptr) {
    asm volatile("cp.async.ca.shared.global [%0], [%1], 16;" :: "r"(saddr), "l"(gptr));
}

// ---------------------------------------------------------------------------
// K1: fused node projections. X[N,64] @ W4T[64,256], cols=[k|q|v|s].
// 256 threads, 64 nodes/block. Thread tile: 4 nodes x 16 m.
// mg=tid>>4 (2 distinct weight addrs/warp -> broadcast), ng=tid&15.
// ---------------------------------------------------------------------------
__global__ __launch_bounds__(256, 2) void node_proj_kernel(
    const float* __restrict__ x,
    const float* __restrict__ Wk, const float* __restrict__ bk,
    const float* __restrict__ Wq, const float* __restrict__ bq,
    const float* __restrict__ Wv, const float* __restrict__ bv,
    const float* __restrict__ Ws, const float* __restrict__ bs,
    int n_nodes)
{
    extern __shared__ float sm[];
    float* w4  = sm;                 // [64][260]  w4[kk][m]
    float* xst = sm + 64 * 260;      // [64][68]   xst[kk][node]
    const int tid = threadIdx.x;

    const float* Wmat[4] = {Wk, Wq, Wv, Ws};
#pragma unroll
    for (int mat = 0; mat < 4; ++mat) {
        const float* W = Wmat[mat];
        for (int idx = tid; idx < 64 * 64; idx += 256) {
            int d = idx >> 6, kk = idx & 63;
            w4[kk * 260 + mat * 64 + d] = W[idx];
        }
    }
    const int nbase = blockIdx.x * 64;
    for (int idx = tid; idx < 64 * 16; idx += 256) {
        int j = idx >> 4, q = idx & 15;
        int n = nbase + j;
        float4 v = make_float4(0.f, 0.f, 0.f, 0.f);
        if (n < n_nodes) v = *(const float4*)&x[(size_t)n * 64 + q * 4];
        xst[(q * 4 + 0) * 68 + j] = v.x;
        xst[(q * 4 + 1) * 68 + j] = v.y;
        xst[(q * 4 + 2) * 68 + j] = v.z;
        xst[(q * 4 + 3) * 68 + j] = v.w;
    }
    __syncthreads();

    const int mg = tid >> 4;     // 0..15 -> m0 = mg*16
    const int ng = tid & 15;     // nodes ng*4 .. +3
    const int m0 = mg * 16;

    unsigned long long acc[4][8];
#pragma unroll
    for (int j = 0; j < 4; ++j)
#pragma unroll
        for (int p = 0; p < 8; ++p) acc[j][p] = 0ULL;

#pragma unroll 4
    for (int kk = 0; kk < 64; ++kk) {
        const float* wrow = &w4[kk * 260 + m0];
        const ulonglong2 wa = *(const ulonglong2*)(wrow);
        const ulonglong2 wb = *(const ulonglong2*)(wrow + 4);
        const ulonglong2 wc = *(const ulonglong2*)(wrow + 8);
        const ulonglong2 wd = *(const ulonglong2*)(wrow + 12);
        const float4 xv = *(const float4*)&xst[kk * 68 + ng * 4];
        unsigned long long xp[4] = {pack_dup(xv.x), pack_dup(xv.y),
                                    pack_dup(xv.z), pack_dup(xv.w)};
#pragma unroll
        for (int j = 0; j < 4; ++j) {
            ffma2(acc[j][0], wa.x, xp[j]); ffma2(acc[j][1], wa.y, xp[j]);
            ffma2(acc[j][2], wb.x, xp[j]); ffma2(acc[j][3], wb.y, xp[j]);
            ffma2(acc[j][4], wc.x, xp[j]); ffma2(acc[j][5], wc.y, xp[j]);
            ffma2(acc[j][6], wd.x, xp[j]); ffma2(acc[j][7], wd.y, xp[j]);
        }
    }

    const int mat = m0 >> 6;
    const int d0  = m0 & 63;     // 0,16,32,48
    const float* bmat[4] = {bk, bq, bv, bs};
    float bb[16];
#pragma unroll
    for (int i = 0; i < 16; ++i) bb[i] = bmat[mat][d0 + i];
    float* omat[4] = {g_k, g_q, g_v, g_agg};
    float* op = omat[mat];

#pragma unroll
    for (int j = 0; j < 4; ++j) {
        int n = nbase + ng * 4 + j;
        if (n < n_nodes) {
            float r[16];
#pragma unroll
            for (int p = 0; p < 8; ++p) {
                float2 a = unpack2(acc[j][p]);
                r[2 * p] = a.x + bb[2 * p];
                r[2 * p + 1] = a.y + bb[2 * p + 1];
            }
            float* dst = &op[(size_t)n * 64 + d0];
            *(float4*)(dst)      = make_float4(r[0], r[1], r[2], r[3]);
            *(float4*)(dst + 4)  = make_float4(r[4], r[5], r[6], r[7]);
            *(float4*)(dst + 8)  = make_float4(r[8], r[9], r[10], r[11]);
            *(float4*)(dst + 12) = make_float4(r[12], r[13], r[14], r[15]);
        }
    }
}

// ---------------------------------------------------------------------------
// K2: edge kernel, 64 edges/block, 256 threads.
// Phase A: cp.async-prefetch k[dst], q[src], v[src] rows into SMEM (3K
//          independent 16B copies -> gather latency hidden under GEMM).
//          Stream edge_attr in (ldcs) transposed to SMEM + pass-through (stcs).
// Phase B: e = ea @ We^T (FFMA2, thread tile 2 edges x 8 d).
// Phase C: msg = sigmoid(k_i+q_j+2e)*(v_j+e); red.global.add.v4 into g_agg.
// ---------------------------------------------------------------------------
__global__ __launch_bounds__(256, 2) void edge_kernel(
    const float* __restrict__ edge_attr,
    const int* __restrict__ ei,             // [2, E] int32
    const float* __restrict__ We, const float* __restrict__ be,
    float* __restrict__ out_ea,
    int n_edges)
{
    extern __shared__ float sm[];
    float* wet  = sm;                // [64][68]  wet[kk][d]
    float* east = sm + 4352;         // [64][68]  east[kk][edge]
    float* gks  = sm + 2 * 4352;     // [64][68]  gathered k[dst], row-major/edge
    float* gqs  = sm + 3 * 4352;     // [64][68]  gathered q[src]
    float* gvs  = sm + 4 * 4352;     // [64][68]  gathered v[src]
    __shared__ int s_src[64];
    __shared__ int s_dst[64];
    const int tid = threadIdx.x;

    const int ebase  = blockIdx.x * 64;
    const int ecount = min(64, n_edges - ebase);
    if (tid < 64 && tid < ecount) {
        s_src[tid] = ei[ebase + tid];
        s_dst[tid] = ei[(size_t)n_edges + ebase + tid];
    }
    __syncthreads();

    // Phase A1: issue all gather cp.asyncs first (maximum prefetch distance).
    {
        const unsigned int smem_u32 =
            (unsigned int)__cvta_generic_to_shared(sm);
        // 64 edges x 16 chunks = 1024 per array; 4 iters of 256 threads.
#pragma unroll
        for (int it = 0; it < 4; ++it) {
            int idx = tid + it * 256;
            int j = idx >> 4, q = idx & 15;
            if (j < ecount) {
                const int src = s_src[j];
                const int dst = s_dst[j];
                unsigned int so = (unsigned int)((j * 68 + q * 4) * 4);
                cp_async16(smem_u32 + (2 * 4352) * 4 + so, &g_k[(size_t)dst * 64 + q * 4]);
                cp_async16(smem_u32 + (3 * 4352) * 4 + so, &g_q[(size_t)src * 64 + q * 4]);
                cp_async16(smem_u32 + (4 * 4352) * 4 + so, &g_v[(size_t)src * 64 + q * 4]);
            }
        }
        asm volatile("cp.async.commit_group;");
    }

    // Phase A2: weights + streamed edge_attr (transposed) + pass-through copy.
    for (int idx = tid; idx < 64 * 64; idx += 256) {
        int d = idx >> 6, kk = idx & 63;
        wet[kk * 68 + d] = We[idx];
    }
#pragma unroll
    for (int it = 0; it < 4; ++it) {
        int idx = tid + it * 256;
        int j = idx >> 4, q = idx & 15;
        float4 v = make_float4(0.f, 0.f, 0.f, 0.f);
        if (j < ecount) {
            const float4* gp = (const float4*)&edge_attr[(size_t)(ebase + j) * 64 + q * 4];
            v = __ldcs(gp);
            if (out_ea) __stcs((float4*)&out_ea[(size_t)(ebase + j) * 64 + q * 4], v);
        }
        east[(q * 4 + 0) * 68 + j] = v.x;
        east[(q * 4 + 1) * 68 + j] = v.y;
        east[(q * 4 + 2) * 68 + j] = v.z;
        east[(q * 4 + 3) * 68 + j] = v.w;
    }
    __syncthreads();

    // Phase B: GEMM. dg=tid&7 -> d0; eg=tid>>3 -> edges eg*2, eg*2+1.
    const int dg = tid & 7;
    const int eg = tid >> 3;
    const int d0 = dg * 8;

    unsigned long long acc[2][4];
#pragma unroll
    for (int j = 0; j < 2; ++j)
#pragma unroll
        for (int p = 0; p < 4; ++p) acc[j][p] = 0ULL;

#pragma unroll 8
    for (int kk = 0; kk < 64; ++kk) {
        const ulonglong2 w01 = *(const ulonglong2*)&wet[kk * 68 + d0];
        const ulonglong2 w23 = *(const ulonglong2*)&wet[kk * 68 + d0 + 4];
        const float2 av = *(const float2*)&east[kk * 68 + eg * 2];
        const unsigned long long a0 = pack_dup(av.x);
        const unsigned long long a1 = pack_dup(av.y);
        ffma2(acc[0][0], w01.x, a0); ffma2(acc[0][1], w01.y, a0);
        ffma2(acc[0][2], w23.x, a0); ffma2(acc[0][3], w23.y, a0);
        ffma2(acc[1][0], w01.x, a1); ffma2(acc[1][1], w01.y, a1);
        ffma2(acc[1][2], w23.x, a1); ffma2(acc[1][3], w23.y, a1);
    }

    float be8[8];
#pragma unroll
    for (int i = 0; i < 8; ++i) be8[i] = be[d0 + i];

    // Gathers must be visible to all threads.
    asm volatile("cp.async.wait_group 0;" ::: "memory");
    __syncthreads();

    // Phase C: gate + scatter.
#pragma unroll
    for (int j = 0; j < 2; ++j) {
        const int e = eg * 2 + j;
        if (e < ecount) {
            float kd[8], qs[8], vs[8];
            *(float4*)&kd[0] = *(const float4*)&gks[e * 68 + d0];
            *(float4*)&kd[4] = *(const float4*)&gks[e * 68 + d0 + 4];
            *(float4*)&qs[0] = *(const float4*)&gqs[e * 68 + d0];
            *(float4*)&qs[4] = *(const float4*)&gqs[e * 68 + d0 + 4];
            *(float4*)&vs[0] = *(const float4*)&gvs[e * 68 + d0];
            *(float4*)&vs[4] = *(const float4*)&gvs[e * 68 + d0 + 4];
            float ev8[8];
            float2 a0 = unpack2(acc[j][0]), a1 = unpack2(acc[j][1]);
            float2 a2 = unpack2(acc[j][2]), a3 = unpack2(acc[j][3]);
            ev8[0] = a0.x; ev8[1] = a0.y; ev8[2] = a1.x; ev8[3] = a1.y;
            ev8[4] = a2.x; ev8[5] = a2.y; ev8[6] = a3.x; ev8[7] = a3.y;
            float m[8];
#pragma unroll
            for (int i = 0; i < 8; ++i) {
                const float ev   = ev8[i] + be8[i];
                const float z    = kd[i] + qs[i] + 2.f * ev;
                const float gate = 1.f / (1.f + __expf(-z));
                m[i] = gate * (vs[i] + ev);
            }
            const int dst = s_dst[e];
            float* ap = &g_agg[(size_t)dst * 64 + d0];
            red_add_v4(ap,     m[0], m[1], m[2], m[3]);
            red_add_v4(ap + 4, m[4], m[5], m[6], m[7]);
        }
    }
}

// ---------------------------------------------------------------------------
// K3: out = relu(g_agg); copy u; cast edge_index -> float32.
// ---------------------------------------------------------------------------
__global__ __launch_bounds__(256) void finalize_kernel(
    float* __restrict__ out,
    const float* __restrict__ u,
    const int* __restrict__ ei,
    int n_nodes, int n_edges, int g_elems, int write_u, int write_ei)
{
    const size_t nd     = (size_t)n_nodes * 64;
    const size_t ed     = (size_t)n_edges * 64;
    const size_t stride = (size_t)gridDim.x * blockDim.x;
    const size_t t0     = (size_t)blockIdx.x * blockDim.x + threadIdx.x;

    for (size_t i = t0; i < nd; i += stride)
        out[i] = fmaxf(g_agg[i], 0.f);

    if (write_u) {
        float* ou = out + nd + ed;
        for (size_t i = t0; i < (size_t)g_elems; i += stride)
            ou[i] = u[i];
    }
    if (write_ei) {
        float* oe = out + nd + ed + g_elems;
        const size_t ne2 = 2 * (size_t)n_edges;
        for (size_t i = t0; i < ne2; i += stride)
            oe[i] = (float)ei[i];
    }
}

extern "C" void kernel_launch(void* const* d_in, const int* in_sizes, int n_in,
                              void* d_out, int out_size) {
    const float* x  = (const float*)d_in[0];
    const int*   ei = (const int*)d_in[1];
    const float* ea = (const float*)d_in[2];
    const float* u  = (const float*)d_in[3];
    const float* Wk = (const float*)d_in[5];  const float* bk = (const float*)d_in[6];
    const float* Wq = (const float*)d_in[7];  const float* bq = (const float*)d_in[8];
    const float* Wv = (const float*)d_in[9];  const float* bv = (const float*)d_in[10];
    const float* We = (const float*)d_in[11]; const float* be = (const float*)d_in[12];
    const float* Ws = (const float*)d_in[13]; const float* bs = (const float*)d_in[14];

    const int n_nodes = in_sizes[0] / 64;
    const int n_edges = in_sizes[2] / 64;
    const int g_elems = in_sizes[3];
    float* out = (float*)d_out;

    const size_t nd = (size_t)n_nodes * 64;
    const size_t ed = (size_t)n_edges * 64;
    const int write_ea = ((size_t)out_size >= nd + ed);
    const int write_u  = ((size_t)out_size >= nd + ed + (size_t)g_elems);
    const int write_ei = ((size_t)out_size >= nd + ed + (size_t)g_elems + 2 * (size_t)n_edges);

    const int smem_node = (64 * 260 + 64 * 68) * 4;   // 83968 B
    const int smem_edge = (5 * 4352) * 4;             // 87040 B
    cudaFuncSetAttribute(node_proj_kernel, cudaFuncAttributeMaxDynamicSharedMemorySize, smem_node);
    cudaFuncSetAttribute(edge_kernel,      cudaFuncAttributeMaxDynamicSharedMemorySize, smem_edge);

    const int nb1 = (n_nodes + 63) / 64;
    node_proj_kernel<<<nb1, 256, smem_node>>>(x, Wk, bk, Wq, bq, Wv, bv, Ws, bs, n_nodes);

    const int nb2 = (n_edges + 63) / 64;
    edge_kernel<<<nb2, 256, smem_edge>>>(ea, ei, We, be,
                                         write_ea ? out + nd : nullptr, n_edges);

    finalize_kernel<<<2048, 256>>>(out, u, ei, n_nodes, n_edges, g_elems, write_u, write_ei);
}

// round 5
// speedup vs baseline: 1.3609x; 1.3609x over previous
#include <cuda_runtime.h>
#include <cstdint>

#define NMAX 100000
#define DD 64

static __device__ float g_k[NMAX * DD];
static __device__ float g_q[NMAX * DD];
static __device__ float g_v[NMAX * DD];
static __device__ float g_agg[NMAX * DD];

__device__ __forceinline__ void red_add_v4(float* p, float a, float b, float c, float d) {
    asm volatile("red.global.add.v4.f32 [%0], {%1,%2,%3,%4};"
                 :: "l"(p), "f"(a), "f"(b), "f"(c), "f"(d) : "memory");
}
__device__ __forceinline__ unsigned long long pack_dup(float v) {
    unsigned long long r;
    asm("mov.b64 %0, {%1, %2};" : "=l"(r) : "f"(v), "f"(v));
    return r;
}
__device__ __forceinline__ void ffma2(unsigned long long& d,
                                      unsigned long long a, unsigned long long b) {
    asm("fma.rn.f32x2 %0, %1, %2, %0;" : "+l"(d) : "l"(a), "l"(b));
}
__device__ __forceinline__ float2 unpack2(unsigned long long v) {
    float lo, hi;
    asm("mov.b64 {%0, %1}, %2;" : "=f"(lo), "=f"(hi) : "l"(v));
    return make_float2(lo, hi);
}

// ---------------------------------------------------------------------------
// K1 (R3-proven): fused node projections. X[N,64] @ W4T[64,256], cols=[k|q|v|s].
// 256 threads, 32 nodes/block. Thread tile: 4 nodes x 8 m.
// ---------------------------------------------------------------------------
__global__ __launch_bounds__(256) void node_proj_kernel(
    const float* __restrict__ x,
    const float* __restrict__ Wk, const float* __restrict__ bk,
    const float* __restrict__ Wq, const float* __restrict__ bq,
    const float* __restrict__ Wv, const float* __restrict__ bv,
    const float* __restrict__ Ws, const float* __restrict__ bs,
    int n_nodes)
{
    extern __shared__ float sm[];
    float* w4  = sm;                 // [64][260]  w4[kk][m]
    float* xst = sm + 64 * 260;      // [64][36]   xst[kk][node]
    const int tid = threadIdx.x;

    const float* Wmat[4] = {Wk, Wq, Wv, Ws};
#pragma unroll
    for (int mat = 0; mat < 4; ++mat) {
        const float* W = Wmat[mat];
        for (int idx = tid; idx < 64 * 64; idx += 256) {
            int d = idx >> 6, kk = idx & 63;
            w4[kk * 260 + mat * 64 + d] = W[idx];
        }
    }
    const int nbase = blockIdx.x * 32;
    for (int idx = tid; idx < 32 * 16; idx += 256) {
        int j = idx >> 4, q = idx & 15;
        int n = nbase + j;
        float4 v = make_float4(0.f, 0.f, 0.f, 0.f);
        if (n < n_nodes) v = *(const float4*)&x[(size_t)n * 64 + q * 4];
        xst[(q * 4 + 0) * 36 + j] = v.x;
        xst[(q * 4 + 1) * 36 + j] = v.y;
        xst[(q * 4 + 2) * 36 + j] = v.z;
        xst[(q * 4 + 3) * 36 + j] = v.w;
    }
    __syncthreads();

    const int mg = tid >> 3;     // m0 = mg*8
    const int ng = tid & 7;      // nodes ng*4 .. +3
    const int m0 = mg * 8;

    unsigned long long acc[4][4];
#pragma unroll
    for (int j = 0; j < 4; ++j)
#pragma unroll
        for (int p = 0; p < 4; ++p) acc[j][p] = 0ULL;

#pragma unroll 8
    for (int kk = 0; kk < 64; ++kk) {
        const ulonglong2 w01 = *(const ulonglong2*)&w4[kk * 260 + m0];
        const ulonglong2 w23 = *(const ulonglong2*)&w4[kk * 260 + m0 + 4];
        const float4 xv = *(const float4*)&xst[kk * 36 + ng * 4];
        unsigned long long xp[4] = {pack_dup(xv.x), pack_dup(xv.y),
                                    pack_dup(xv.z), pack_dup(xv.w)};
#pragma unroll
        for (int j = 0; j < 4; ++j) {
            ffma2(acc[j][0], w01.x, xp[j]);
            ffma2(acc[j][1], w01.y, xp[j]);
            ffma2(acc[j][2], w23.x, xp[j]);
            ffma2(acc[j][3], w23.y, xp[j]);
        }
    }

    const int mat = m0 >> 6;
    const int d0  = m0 & 63;
    const float* bmat[4] = {bk, bq, bv, bs};
    float bb[8];
#pragma unroll
    for (int i = 0; i < 8; ++i) bb[i] = bmat[mat][d0 + i];
    float* omat[4] = {g_k, g_q, g_v, g_agg};
    float* op = omat[mat];

#pragma unroll
    for (int j = 0; j < 4; ++j) {
        int n = nbase + ng * 4 + j;
        if (n < n_nodes) {
            float2 a0 = unpack2(acc[j][0]), a1 = unpack2(acc[j][1]);
            float2 a2 = unpack2(acc[j][2]), a3 = unpack2(acc[j][3]);
            float4 r0 = make_float4(a0.x + bb[0], a0.y + bb[1], a1.x + bb[2], a1.y + bb[3]);
            float4 r1 = make_float4(a2.x + bb[4], a2.y + bb[5], a3.x + bb[6], a3.y + bb[7]);
            *(float4*)&op[(size_t)n * 64 + d0]     = r0;
            *(float4*)&op[(size_t)n * 64 + d0 + 4] = r1;
        }
    }
}

// ---------------------------------------------------------------------------
// K2: edge kernel, 128 edges/block (R3 structure), with a guard-free fast
// path for full tiles (7812/7813 blocks): gather loads batched 2 edges at a
// time (12 LDG.128 in flight), REDs unconditional.
// ---------------------------------------------------------------------------
__global__ __launch_bounds__(256) void edge_kernel(
    const float* __restrict__ edge_attr,
    const int* __restrict__ ei,             // [2, E] int32
    const float* __restrict__ We, const float* __restrict__ be,
    float* __restrict__ out_ea,
    int n_edges)
{
    extern __shared__ float sm[];
    float* wet  = sm;               // [64][68]  wet[kk][d]
    float* east = sm + 64 * 68;     // [64][132] east[kk][edge]
    __shared__ int s_src[128];
    __shared__ int s_dst[128];
    const int tid = threadIdx.x;

    for (int idx = tid; idx < 64 * 64; idx += 256) {
        int d = idx >> 6, kk = idx & 63;
        wet[kk * 68 + d] = We[idx];
    }
    const int ebase  = blockIdx.x * 128;
    const int ecount = min(128, n_edges - ebase);
    // transposed fill + fused pass-through copy (streaming hints: zero reuse)
    for (int idx = tid; idx < 128 * 16; idx += 256) {
        int j = idx >> 4, q = idx & 15;
        float4 v = make_float4(0.f, 0.f, 0.f, 0.f);
        if (j < ecount) {
            size_t g = (size_t)(ebase + j) * 64 + q * 4;
            v = __ldcs((const float4*)&edge_attr[g]);
            if (out_ea) __stcs((float4*)&out_ea[g], v);
        }
        east[(q * 4 + 0) * 132 + j] = v.x;
        east[(q * 4 + 1) * 132 + j] = v.y;
        east[(q * 4 + 2) * 132 + j] = v.z;
        east[(q * 4 + 3) * 132 + j] = v.w;
    }
    if (tid < 128 && tid < ecount) {
        s_src[tid] = ei[ebase + tid];
        s_dst[tid] = ei[(size_t)n_edges + ebase + tid];
    }
    __syncthreads();

    const int dg = tid & 7;    // d0 = dg*8
    const int eg = tid >> 3;   // edges eg*4 .. +3
    const int d0 = dg * 8;

    float be8[8];
#pragma unroll
    for (int i = 0; i < 8; ++i) be8[i] = be[d0 + i];

    unsigned long long acc[4][4];
#pragma unroll
    for (int j = 0; j < 4; ++j)
#pragma unroll
        for (int p = 0; p < 4; ++p) acc[j][p] = 0ULL;

#pragma unroll 8
    for (int kk = 0; kk < 64; ++kk) {
        const ulonglong2 w01 = *(const ulonglong2*)&wet[kk * 68 + d0];
        const ulonglong2 w23 = *(const ulonglong2*)&wet[kk * 68 + d0 + 4];
        const float4 av = *(const float4*)&east[kk * 132 + eg * 4];
        unsigned long long ap[4] = {pack_dup(av.x), pack_dup(av.y),
                                    pack_dup(av.z), pack_dup(av.w)};
#pragma unroll
        for (int j = 0; j < 4; ++j) {
            ffma2(acc[j][0], w01.x, ap[j]);
            ffma2(acc[j][1], w01.y, ap[j]);
            ffma2(acc[j][2], w23.x, ap[j]);
            ffma2(acc[j][3], w23.y, ap[j]);
        }
    }

    if (ecount == 128) {
        // fast path: no guards -> gather LDGs batch freely (2 edges = 12 LDG.128)
#pragma unroll
        for (int jp = 0; jp < 4; jp += 2) {
            int e0 = eg * 4 + jp;
            int e1 = e0 + 1;
            const int src0 = s_src[e0], dst0 = s_dst[e0];
            const int src1 = s_src[e1], dst1 = s_dst[e1];
            float kd0[8], qs0[8], vs0[8], kd1[8], qs1[8], vs1[8];
            *(float4*)&kd0[0] = *(const float4*)&g_k[(size_t)dst0 * 64 + d0];
            *(float4*)&kd0[4] = *(const float4*)&g_k[(size_t)dst0 * 64 + d0 + 4];
            *(float4*)&qs0[0] = *(const float4*)&g_q[(size_t)src0 * 64 + d0];
            *(float4*)&qs0[4] = *(const float4*)&g_q[(size_t)src0 * 64 + d0 + 4];
            *(float4*)&vs0[0] = *(const float4*)&g_v[(size_t)src0 * 64 + d0];
            *(float4*)&vs0[4] = *(const float4*)&g_v[(size_t)src0 * 64 + d0 + 4];
            *(float4*)&kd1[0] = *(const float4*)&g_k[(size_t)dst1 * 64 + d0];
            *(float4*)&kd1[4] = *(const float4*)&g_k[(size_t)dst1 * 64 + d0 + 4];
            *(float4*)&qs1[0] = *(const float4*)&g_q[(size_t)src1 * 64 + d0];
            *(float4*)&qs1[4] = *(const float4*)&g_q[(size_t)src1 * 64 + d0 + 4];
            *(float4*)&vs1[0] = *(const float4*)&g_v[(size_t)src1 * 64 + d0];
            *(float4*)&vs1[4] = *(const float4*)&g_v[(size_t)src1 * 64 + d0 + 4];

            float m0v[8], m1v[8];
            {
                float ev8[8];
                float2 a0 = unpack2(acc[jp][0]), a1 = unpack2(acc[jp][1]);
                float2 a2 = unpack2(acc[jp][2]), a3 = unpack2(acc[jp][3]);
                ev8[0] = a0.x; ev8[1] = a0.y; ev8[2] = a1.x; ev8[3] = a1.y;
                ev8[4] = a2.x; ev8[5] = a2.y; ev8[6] = a3.x; ev8[7] = a3.y;
#pragma unroll
                for (int i = 0; i < 8; ++i) {
                    const float ev   = ev8[i] + be8[i];
                    const float z    = kd0[i] + qs0[i] + 2.f * ev;
                    const float gate = 1.f / (1.f + __expf(-z));
                    m0v[i] = gate * (vs0[i] + ev);
                }
            }
            {
                float ev8[8];
                float2 a0 = unpack2(acc[jp + 1][0]), a1 = unpack2(acc[jp + 1][1]);
                float2 a2 = unpack2(acc[jp + 1][2]), a3 = unpack2(acc[jp + 1][3]);
                ev8[0] = a0.x; ev8[1] = a0.y; ev8[2] = a1.x; ev8[3] = a1.y;
                ev8[4] = a2.x; ev8[5] = a2.y; ev8[6] = a3.x; ev8[7] = a3.y;
#pragma unroll
                for (int i = 0; i < 8; ++i) {
                    const float ev   = ev8[i] + be8[i];
                    const float z    = kd1[i] + qs1[i] + 2.f * ev;
                    const float gate = 1.f / (1.f + __expf(-z));
                    m1v[i] = gate * (vs1[i] + ev);
                }
            }
            float* ap0 = &g_agg[(size_t)dst0 * 64 + d0];
            float* ap1 = &g_agg[(size_t)dst1 * 64 + d0];
            red_add_v4(ap0,     m0v[0], m0v[1], m0v[2], m0v[3]);
            red_add_v4(ap0 + 4, m0v[4], m0v[5], m0v[6], m0v[7]);
            red_add_v4(ap1,     m1v[0], m1v[1], m1v[2], m1v[3]);
            red_add_v4(ap1 + 4, m1v[4], m1v[5], m1v[6], m1v[7]);
        }
    } else {
        // guarded tail path (1 block)
#pragma unroll
        for (int j = 0; j < 4; ++j) {
            int e = eg * 4 + j;
            if (e < ecount) {
                const int src = s_src[e];
                const int dst = s_dst[e];
                float kd[8], qs[8], vs[8];
                *(float4*)&kd[0] = *(const float4*)&g_k[(size_t)dst * 64 + d0];
                *(float4*)&kd[4] = *(const float4*)&g_k[(size_t)dst * 64 + d0 + 4];
                *(float4*)&qs[0] = *(const float4*)&g_q[(size_t)src * 64 + d0];
                *(float4*)&qs[4] = *(const float4*)&g_q[(size_t)src * 64 + d0 + 4];
                *(float4*)&vs[0] = *(const float4*)&g_v[(size_t)src * 64 + d0];
                *(float4*)&vs[4] = *(const float4*)&g_v[(size_t)src * 64 + d0 + 4];
                float ev8[8];
                float2 a0 = unpack2(acc[j][0]), a1 = unpack2(acc[j][1]);
                float2 a2 = unpack2(acc[j][2]), a3 = unpack2(acc[j][3]);
                ev8[0] = a0.x; ev8[1] = a0.y; ev8[2] = a1.x; ev8[3] = a1.y;
                ev8[4] = a2.x; ev8[5] = a2.y; ev8[6] = a3.x; ev8[7] = a3.y;
                float m[8];
#pragma unroll
                for (int i = 0; i < 8; ++i) {
                    const float ev   = ev8[i] + be8[i];
                    const float z    = kd[i] + qs[i] + 2.f * ev;
                    const float gate = 1.f / (1.f + __expf(-z));
                    m[i] = gate * (vs[i] + ev);
                }
                float* ap = &g_agg[(size_t)dst * 64 + d0];
                red_add_v4(ap,     m[0], m[1], m[2], m[3]);
                red_add_v4(ap + 4, m[4], m[5], m[6], m[7]);
            }
        }
    }
}

// ---------------------------------------------------------------------------
// K3: out = relu(g_agg) (float4); copy u; cast edge_index -> float32.
// ---------------------------------------------------------------------------
__global__ __launch_bounds__(256) void finalize_kernel(
    float* __restrict__ out,
    const float* __restrict__ u,
    const int* __restrict__ ei,
    int n_nodes, int n_edges, int g_elems, int write_u, int write_ei)
{
    const size_t nd     = (size_t)n_nodes * 64;
    const size_t ed     = (size_t)n_edges * 64;
    const size_t stride = (size_t)gridDim.x * blockDim.x;
    const size_t t0     = (size_t)blockIdx.x * blockDim.x + threadIdx.x;

    const size_t nd4 = nd >> 2;
    const float4* agg4 = (const float4*)g_agg;
    float4* out4 = (float4*)out;
    for (size_t i = t0; i < nd4; i += stride) {
        float4 v = agg4[i];
        v.x = fmaxf(v.x, 0.f); v.y = fmaxf(v.y, 0.f);
        v.z = fmaxf(v.z, 0.f); v.w = fmaxf(v.w, 0.f);
        out4[i] = v;
    }

    if (write_u) {
        float* ou = out + nd + ed;
        for (size_t i = t0; i < (size_t)g_elems; i += stride)
            ou[i] = u[i];
    }
    if (write_ei) {
        float* oe = out + nd + ed + g_elems;
        const size_t ne2 = 2 * (size_t)n_edges;
        for (size_t i = t0; i < ne2; i += stride)
            oe[i] = (float)ei[i];
    }
}

extern "C" void kernel_launch(void* const* d_in, const int* in_sizes, int n_in,
                              void* d_out, int out_size) {
    const float* x  = (const float*)d_in[0];
    const int*   ei = (const int*)d_in[1];
    const float* ea = (const float*)d_in[2];
    const float* u  = (const float*)d_in[3];
    const float* Wk = (const float*)d_in[5];  const float* bk = (const float*)d_in[6];
    const float* Wq = (const float*)d_in[7];  const float* bq = (const float*)d_in[8];
    const float* Wv = (const float*)d_in[9];  const float* bv = (const float*)d_in[10];
    const float* We = (const float*)d_in[11]; const float* be = (const float*)d_in[12];
    const float* Ws = (const float*)d_in[13]; const float* bs = (const float*)d_in[14];

    const int n_nodes = in_sizes[0] / 64;
    const int n_edges = in_sizes[2] / 64;
    const int g_elems = in_sizes[3];
    float* out = (float*)d_out;

    const size_t nd = (size_t)n_nodes * 64;
    const size_t ed = (size_t)n_edges * 64;
    const int write_ea = ((size_t)out_size >= nd + ed);
    const int write_u  = ((size_t)out_size >= nd + ed + (size_t)g_elems);
    const int write_ei = ((size_t)out_size >= nd + ed + (size_t)g_elems + 2 * (size_t)n_edges);

    const int smem_node = (64 * 260 + 64 * 36) * 4;   // 75776 B
    const int smem_edge = (64 * 68 + 64 * 132) * 4;   // 51200 B
    cudaFuncSetAttribute(node_proj_kernel, cudaFuncAttributeMaxDynamicSharedMemorySize, smem_node);
    cudaFuncSetAttribute(edge_kernel,      cudaFuncAttributeMaxDynamicSharedMemorySize, smem_edge);

    const int nb1 = (n_nodes + 31) / 32;
    node_proj_kernel<<<nb1, 256, smem_node>>>(x, Wk, bk, Wq, bq, Wv, bv, Ws, bs, n_nodes);

    const int nb2 = (n_edges + 127) / 128;
    edge_kernel<<<nb2, 256, smem_edge>>>(ea, ei, We, be,
                                         write_ea ? out + nd : nullptr, n_edges);

    finalize_kernel<<<2048, 256>>>(out, u, ei, n_nodes, n_edges, g_elems, write_u, write_ei);
}